// round 1
// baseline (speedup 1.0000x reference)
#include <cuda_runtime.h>
#include <cstdint>
#include <math.h>

#define H 1024
#define IDIM 4096
#define NE 8
#define T_TOK 8192
#define NSLOT (2 * T_TOK)

// ---------------- device scratch (no allocations allowed) ----------------
__device__ int   g_count[NE];
__device__ int   g_base[NE];
__device__ int   g_tok[NE * T_TOK];
__device__ float g_wt[NE * T_TOK];
__device__ float g_probs[T_TOK * NE];
// hidden activations, padded by 128 rows so GEMM2 tiles may read past base+cnt
__device__ float g_h[(size_t)(NSLOT + 128) * IDIM];

// ---------------- helpers ----------------
__device__ __forceinline__ unsigned tf32b(float f) {
    unsigned u;
    asm("cvt.rna.tf32.f32 %0, %1;" : "=r"(u) : "f"(f));
    return u;
}

__device__ __forceinline__ void mma_tf32(float* d, const unsigned* a, const unsigned* b) {
    asm volatile(
        "mma.sync.aligned.m16n8k8.row.col.f32.tf32.tf32.f32 "
        "{%0,%1,%2,%3}, {%4,%5,%6,%7}, {%8,%9}, {%0,%1,%2,%3};\n"
        : "+f"(d[0]), "+f"(d[1]), "+f"(d[2]), "+f"(d[3])
        : "r"(a[0]), "r"(a[1]), "r"(a[2]), "r"(a[3]), "r"(b[0]), "r"(b[1]));
}

// ---------------- zero / init ----------------
__global__ void zero_out_kernel(float* out, int n) {
    int i = blockIdx.x * blockDim.x + threadIdx.x;
    int stride = gridDim.x * blockDim.x;
    if (i < NE) g_count[i] = 0;
    for (; i < n; i += stride) out[i] = 0.0f;
}

// ---------------- gating: logits, softmax, top-2, routing ----------------
__global__ __launch_bounds__(256) void gating_kernel(const float* __restrict__ x,
                                                     const float* __restrict__ gw) {
    __shared__ float sgw[NE * H];  // 32KB
    for (int i = threadIdx.x; i < NE * H; i += blockDim.x) sgw[i] = gw[i];
    __syncthreads();

    int warp = threadIdx.x >> 5, lane = threadIdx.x & 31;
    int t = blockIdx.x * 8 + warp;
    const float* xr = x + (size_t)t * H;

    float acc[NE];
#pragma unroll
    for (int e = 0; e < NE; e++) acc[e] = 0.0f;
    for (int k = lane; k < H; k += 32) {
        float xv = xr[k];
#pragma unroll
        for (int e = 0; e < NE; e++) acc[e] += xv * sgw[e * H + k];
    }
#pragma unroll
    for (int e = 0; e < NE; e++) {
#pragma unroll
        for (int off = 16; off; off >>= 1)
            acc[e] += __shfl_xor_sync(0xffffffffu, acc[e], off);
    }

    if (lane == 0) {
        float mx = acc[0];
#pragma unroll
        for (int e = 1; e < NE; e++) mx = fmaxf(mx, acc[e]);
        float p[NE], s = 0.0f;
#pragma unroll
        for (int e = 0; e < NE; e++) { p[e] = expf(acc[e] - mx); s += p[e]; }
        float inv = 1.0f / s;
#pragma unroll
        for (int e = 0; e < NE; e++) { p[e] *= inv; g_probs[t * NE + e] = p[e]; }

        int b0 = 0;
#pragma unroll
        for (int e = 1; e < NE; e++) if (p[e] > p[b0]) b0 = e;
        int b1 = (b0 == 0) ? 1 : 0;
#pragma unroll
        for (int e = 0; e < NE; e++) if (e != b0 && p[e] > p[b1]) b1 = e;

        float d = 1.0f / (p[b0] + p[b1] + 1e-9f);
        int pos0 = atomicAdd(&g_count[b0], 1);
        g_tok[b0 * T_TOK + pos0] = t;
        g_wt[b0 * T_TOK + pos0] = p[b0] * d;
        int pos1 = atomicAdd(&g_count[b1], 1);
        g_tok[b1 * T_TOK + pos1] = t;
        g_wt[b1 * T_TOK + pos1] = p[b1] * d;
    }
}

// ---------------- prefix scan + aux loss (deterministic reduction) ----------------
__global__ void scan_aux_kernel(float* out) {
    __shared__ float red[256];
    __shared__ float imp[NE];
    float s[NE];
#pragma unroll
    for (int e = 0; e < NE; e++) s[e] = 0.0f;
    for (int i = threadIdx.x; i < T_TOK; i += 256) {
#pragma unroll
        for (int e = 0; e < NE; e++) s[e] += g_probs[i * NE + e];
    }
    for (int e = 0; e < NE; e++) {
        red[threadIdx.x] = s[e];
        __syncthreads();
        for (int off = 128; off; off >>= 1) {
            if (threadIdx.x < off) red[threadIdx.x] += red[threadIdx.x + off];
            __syncthreads();
        }
        if (threadIdx.x == 0) imp[e] = red[0];
        __syncthreads();
    }
    if (threadIdx.x == 0) {
        int b = 0;
        float aux = 0.0f;
        for (int e = 0; e < NE; e++) {
            g_base[e] = b;
            b += g_count[e];
            float usage = (float)g_count[e] / ((float)(T_TOK * 2) + 1e-9f);
            float importance = imp[e] / (float)T_TOK;
            aux += usage * importance;
        }
        aux = fminf(aux * (float)NE * 0.01f, 1.0f);
        out[(size_t)T_TOK * H] = aux;
    }
}

// ---------------- GEMM1: h = silu(x@Wg^T) * (x@Wu^T), tf32 tensor cores ----------------
#define BM1 128
#define BN1 64
#define BK 32
#define KSTR (BK + 4)  // 36, conflict-free for frag access & 16B-aligned rows

__global__ __launch_bounds__(256, 1) void gemm1_kernel(const float* __restrict__ x,
                                                       const float* __restrict__ w1) {
    int e = blockIdx.z;
    int cnt = g_count[e];
    int m0 = blockIdx.x * BM1;
    if (m0 >= cnt) return;
    int n0 = blockIdx.y * BN1;

    __shared__ __align__(16) float smem[BM1 * KSTR + 2 * BN1 * KSTR];  // 36KB
    float* As = smem;
    float* Bg = smem + BM1 * KSTR;
    float* Bu = Bg + BN1 * KSTR;

    int tid = threadIdx.x, warp = tid >> 5, lane = tid & 31;
    int g4 = lane >> 2, tig = lane & 3;
    int wm = warp >> 1, wn = warp & 1;

    const float* Wg = w1 + (size_t)e * 2 * IDIM * H + (size_t)n0 * H;
    const float* Wu = Wg + (size_t)IDIM * H;

    // A load plan: 128 rows x 8 float4 = 1024 f4 -> 4 per thread (gathered rows)
    const float* aptr[4];
#pragma unroll
    for (int t = 0; t < 4; t++) {
        int idx = tid + t * 256;
        int r = idx >> 3, c = idx & 7;
        int tok = (m0 + r < cnt) ? g_tok[e * T_TOK + m0 + r] : -1;
        aptr[t] = (tok >= 0) ? x + (size_t)tok * H + c * 4 : nullptr;
    }

    float4 ra[4], rbg[2], rbu[2];

    // prologue load k=0
#pragma unroll
    for (int t = 0; t < 4; t++)
        ra[t] = aptr[t] ? *(const float4*)(aptr[t]) : make_float4(0, 0, 0, 0);
#pragma unroll
    for (int t = 0; t < 2; t++) {
        int idx = tid + t * 256;
        int r = idx >> 3, c = idx & 7;
        rbg[t] = *(const float4*)(Wg + (size_t)r * H + c * 4);
        rbu[t] = *(const float4*)(Wu + (size_t)r * H + c * 4);
    }
    // store to smem (tf32-rounded)
#pragma unroll
    for (int t = 0; t < 4; t++) {
        int idx = tid + t * 256;
        int r = idx >> 3, c = idx & 7;
        uint4 v = {tf32b(ra[t].x), tf32b(ra[t].y), tf32b(ra[t].z), tf32b(ra[t].w)};
        *(uint4*)&As[r * KSTR + c * 4] = v;
    }
#pragma unroll
    for (int t = 0; t < 2; t++) {
        int idx = tid + t * 256;
        int r = idx >> 3, c = idx & 7;
        uint4 vg = {tf32b(rbg[t].x), tf32b(rbg[t].y), tf32b(rbg[t].z), tf32b(rbg[t].w)};
        *(uint4*)&Bg[r * KSTR + c * 4] = vg;
        uint4 vu = {tf32b(rbu[t].x), tf32b(rbu[t].y), tf32b(rbu[t].z), tf32b(rbu[t].w)};
        *(uint4*)&Bu[r * KSTR + c * 4] = vu;
    }
    __syncthreads();

    float accg[2][4][4], accu[2][4][4];
#pragma unroll
    for (int a = 0; a < 2; a++)
#pragma unroll
        for (int b = 0; b < 4; b++)
#pragma unroll
            for (int c = 0; c < 4; c++) { accg[a][b][c] = 0.0f; accu[a][b][c] = 0.0f; }

    const int NKT = H / BK;  // 32
    for (int kt = 0; kt < NKT; kt++) {
        if (kt + 1 < NKT) {
            int k0 = (kt + 1) * BK;
#pragma unroll
            for (int t = 0; t < 4; t++)
                ra[t] = aptr[t] ? *(const float4*)(aptr[t] + k0) : make_float4(0, 0, 0, 0);
#pragma unroll
            for (int t = 0; t < 2; t++) {
                int idx = tid + t * 256;
                int r = idx >> 3, c = idx & 7;
                rbg[t] = *(const float4*)(Wg + (size_t)r * H + k0 + c * 4);
                rbu[t] = *(const float4*)(Wu + (size_t)r * H + k0 + c * 4);
            }
        }
#pragma unroll
        for (int ks = 0; ks < 4; ks++) {
            int kk = ks * 8;
            unsigned a[2][4];
#pragma unroll
            for (int mf = 0; mf < 2; mf++) {
                int r = wm * 32 + mf * 16;
                a[mf][0] = __float_as_uint(As[(r + g4) * KSTR + kk + tig]);
                a[mf][1] = __float_as_uint(As[(r + g4 + 8) * KSTR + kk + tig]);
                a[mf][2] = __float_as_uint(As[(r + g4) * KSTR + kk + tig + 4]);
                a[mf][3] = __float_as_uint(As[(r + g4 + 8) * KSTR + kk + tig + 4]);
            }
            unsigned bg[4][2], bu[4][2];
#pragma unroll
            for (int nf = 0; nf < 4; nf++) {
                int c = wn * 32 + nf * 8 + g4;
                bg[nf][0] = __float_as_uint(Bg[c * KSTR + kk + tig]);
                bg[nf][1] = __float_as_uint(Bg[c * KSTR + kk + tig + 4]);
                bu[nf][0] = __float_as_uint(Bu[c * KSTR + kk + tig]);
                bu[nf][1] = __float_as_uint(Bu[c * KSTR + kk + tig + 4]);
            }
#pragma unroll
            for (int mf = 0; mf < 2; mf++)
#pragma unroll
                for (int nf = 0; nf < 4; nf++) {
                    mma_tf32(accg[mf][nf], a[mf], bg[nf]);
                    mma_tf32(accu[mf][nf], a[mf], bu[nf]);
                }
        }
        __syncthreads();
        if (kt + 1 < NKT) {
#pragma unroll
            for (int t = 0; t < 4; t++) {
                int idx = tid + t * 256;
                int r = idx >> 3, c = idx & 7;
                uint4 v = {tf32b(ra[t].x), tf32b(ra[t].y), tf32b(ra[t].z), tf32b(ra[t].w)};
                *(uint4*)&As[r * KSTR + c * 4] = v;
            }
#pragma unroll
            for (int t = 0; t < 2; t++) {
                int idx = tid + t * 256;
                int r = idx >> 3, c = idx & 7;
                uint4 vg = {tf32b(rbg[t].x), tf32b(rbg[t].y), tf32b(rbg[t].z), tf32b(rbg[t].w)};
                *(uint4*)&Bg[r * KSTR + c * 4] = vg;
                uint4 vu = {tf32b(rbu[t].x), tf32b(rbu[t].y), tf32b(rbu[t].z), tf32b(rbu[t].w)};
                *(uint4*)&Bu[r * KSTR + c * 4] = vu;
            }
            __syncthreads();
        }
    }

    // epilogue: h = silu(g)*u, stage through smem (stride 68 => aligned + low conflict)
    __syncthreads();
    float* Hs = smem;  // 128*68 = 8704 floats <= 9216
#pragma unroll
    for (int mf = 0; mf < 2; mf++)
#pragma unroll
        for (int nf = 0; nf < 4; nf++)
#pragma unroll
            for (int i = 0; i < 4; i++) {
                int row = wm * 32 + mf * 16 + g4 + ((i >= 2) ? 8 : 0);
                int col = wn * 32 + nf * 8 + tig * 2 + (i & 1);
                float gv = accg[mf][nf][i], uv = accu[mf][nf][i];
                float sv = gv / (1.0f + __expf(-gv));
                Hs[row * 68 + col] = sv * uv;
            }
    __syncthreads();

    int mybase = g_base[e];
#pragma unroll
    for (int t = 0; t < 8; t++) {
        int idx = tid + t * 256;
        int r = idx >> 4, c4 = idx & 15;
        if (m0 + r < cnt) {
            float4 v = *(float4*)&Hs[r * 68 + c4 * 4];
            uint4 o = {tf32b(v.x), tf32b(v.y), tf32b(v.z), tf32b(v.w)};
            *(uint4*)&g_h[(size_t)(mybase + m0 + r) * IDIM + n0 + c4 * 4] = o;
        }
    }
}

// ---------------- GEMM2: out[tok] += w * (h @ W2^T) ----------------
#define BM2 128
#define BN2 128

__global__ __launch_bounds__(256, 1) void gemm2_kernel(const float* __restrict__ w2,
                                                       float* __restrict__ out) {
    int e = blockIdx.z;
    int cnt = g_count[e];
    int m0 = blockIdx.x * BM2;
    if (m0 >= cnt) return;
    int n0 = blockIdx.y * BN2;
    int base = g_base[e];

    __shared__ __align__(16) float As[BM2 * KSTR];  // 18KB
    __shared__ __align__(16) float Bs[BN2 * KSTR];  // 18KB

    int tid = threadIdx.x, warp = tid >> 5, lane = tid & 31;
    int g4 = lane >> 2, tig = lane & 3;
    int wm = warp >> 1, wn = warp & 1;

    const float* Ab = g_h + (size_t)(base + m0) * IDIM;
    const float* W = w2 + (size_t)e * H * IDIM + (size_t)n0 * IDIM;

    float4 raa[4], rbb[4];
    // prologue
#pragma unroll
    for (int t = 0; t < 4; t++) {
        int idx = tid + t * 256;
        int r = idx >> 3, c = idx & 7;
        raa[t] = *(const float4*)(Ab + (size_t)r * IDIM + c * 4);
        rbb[t] = *(const float4*)(W + (size_t)r * IDIM + c * 4);
    }
#pragma unroll
    for (int t = 0; t < 4; t++) {
        int idx = tid + t * 256;
        int r = idx >> 3, c = idx & 7;
        *(float4*)&As[r * KSTR + c * 4] = raa[t];  // already tf32-rounded
        uint4 v = {tf32b(rbb[t].x), tf32b(rbb[t].y), tf32b(rbb[t].z), tf32b(rbb[t].w)};
        *(uint4*)&Bs[r * KSTR + c * 4] = v;
    }
    __syncthreads();

    float acc[2][8][4];
#pragma unroll
    for (int a = 0; a < 2; a++)
#pragma unroll
        for (int b = 0; b < 8; b++)
#pragma unroll
            for (int c = 0; c < 4; c++) acc[a][b][c] = 0.0f;

    const int NKT = IDIM / BK;  // 128
    for (int kt = 0; kt < NKT; kt++) {
        if (kt + 1 < NKT) {
            int k0 = (kt + 1) * BK;
#pragma unroll
            for (int t = 0; t < 4; t++) {
                int idx = tid + t * 256;
                int r = idx >> 3, c = idx & 7;
                raa[t] = *(const float4*)(Ab + (size_t)r * IDIM + k0 + c * 4);
                rbb[t] = *(const float4*)(W + (size_t)r * IDIM + k0 + c * 4);
            }
        }
#pragma unroll
        for (int ks = 0; ks < 4; ks++) {
            int kk = ks * 8;
            unsigned a[2][4];
#pragma unroll
            for (int mf = 0; mf < 2; mf++) {
                int r = wm * 32 + mf * 16;
                a[mf][0] = __float_as_uint(As[(r + g4) * KSTR + kk + tig]);
                a[mf][1] = __float_as_uint(As[(r + g4 + 8) * KSTR + kk + tig]);
                a[mf][2] = __float_as_uint(As[(r + g4) * KSTR + kk + tig + 4]);
                a[mf][3] = __float_as_uint(As[(r + g4 + 8) * KSTR + kk + tig + 4]);
            }
            unsigned b[8][2];
#pragma unroll
            for (int nf = 0; nf < 8; nf++) {
                int c = wn * 64 + nf * 8 + g4;
                b[nf][0] = __float_as_uint(Bs[c * KSTR + kk + tig]);
                b[nf][1] = __float_as_uint(Bs[c * KSTR + kk + tig + 4]);
            }
#pragma unroll
            for (int mf = 0; mf < 2; mf++)
#pragma unroll
                for (int nf = 0; nf < 8; nf++) mma_tf32(acc[mf][nf], a[mf], b[nf]);
        }
        __syncthreads();
        if (kt + 1 < NKT) {
#pragma unroll
            for (int t = 0; t < 4; t++) {
                int idx = tid + t * 256;
                int r = idx >> 3, c = idx & 7;
                *(float4*)&As[r * KSTR + c * 4] = raa[t];
                uint4 v = {tf32b(rbb[t].x), tf32b(rbb[t].y), tf32b(rbb[t].z), tf32b(rbb[t].w)};
                *(uint4*)&Bs[r * KSTR + c * 4] = v;
            }
            __syncthreads();
        }
    }

    // epilogue: weighted scatter-add (exactly 2 adds per out element -> deterministic)
#pragma unroll
    for (int mf = 0; mf < 2; mf++) {
#pragma unroll
        for (int half = 0; half < 2; half++) {
            int r = wm * 32 + mf * 16 + g4 + half * 8;
            int gr = m0 + r;
            if (gr < cnt) {
                int tok = g_tok[e * T_TOK + gr];
                float w = g_wt[e * T_TOK + gr];
                float* op = out + (size_t)tok * H + n0 + wn * 64;
#pragma unroll
                for (int nf = 0; nf < 8; nf++) {
                    atomicAdd(op + nf * 8 + tig * 2, w * acc[mf][nf][half * 2 + 0]);
                    atomicAdd(op + nf * 8 + tig * 2 + 1, w * acc[mf][nf][half * 2 + 1]);
                }
            }
        }
    }
}

// ---------------- launch ----------------
extern "C" void kernel_launch(void* const* d_in, const int* in_sizes, int n_in,
                              void* d_out, int out_size) {
    const float* x = (const float*)d_in[0];
    const float* gate_w = (const float*)d_in[1];
    const float* gate_up_w = (const float*)d_in[2];
    const float* down_w = (const float*)d_in[3];
    float* out = (float*)d_out;

    zero_out_kernel<<<4096, 256>>>(out, out_size);
    gating_kernel<<<T_TOK / 8, 256>>>(x, gate_w);
    scan_aux_kernel<<<1, 256>>>(out);

    dim3 g1(T_TOK / BM1, IDIM / BN1, NE);  // (64, 64, 8)
    gemm1_kernel<<<g1, 256>>>(x, gate_up_w);

    dim3 g2(T_TOK / BM2, H / BN2, NE);  // (64, 8, 8)
    gemm2_kernel<<<g2, 256>>>(down_w, out);
}

// round 3
// speedup vs baseline: 1.5649x; 1.5649x over previous
#include <cuda_runtime.h>
#include <cstdint>
#include <math.h>

#define H 1024
#define IDIM 4096
#define NE 8
#define T_TOK 8192
#define NSLOT (2 * T_TOK)

// ---------------- device scratch (no allocations allowed) ----------------
__device__ int   g_count[NE];
__device__ int   g_base[NE];
__device__ int   g_tok[NE * T_TOK];
__device__ float g_wt[NE * T_TOK];
__device__ float g_probs[T_TOK * NE];
// hidden activations, padded by 128 rows so GEMM2 tiles may read past base+cnt
__device__ float g_h[(size_t)(NSLOT + 128) * IDIM];

// ---------------- helpers ----------------
__device__ __forceinline__ unsigned tf32b(float f) {
    unsigned u;
    asm("cvt.rna.tf32.f32 %0, %1;" : "=r"(u) : "f"(f));
    return u;
}

__device__ __forceinline__ void mma_tf32(float* d, const unsigned* a, const unsigned* b) {
    asm volatile(
        "mma.sync.aligned.m16n8k8.row.col.f32.tf32.tf32.f32 "
        "{%0,%1,%2,%3}, {%4,%5,%6,%7}, {%8,%9}, {%0,%1,%2,%3};\n"
        : "+f"(d[0]), "+f"(d[1]), "+f"(d[2]), "+f"(d[3])
        : "r"(a[0]), "r"(a[1]), "r"(a[2]), "r"(a[3]), "r"(b[0]), "r"(b[1]));
}

// ---------------- zero / init ----------------
__global__ void zero_out_kernel(float* out, int n) {
    int i = blockIdx.x * blockDim.x + threadIdx.x;
    int stride = gridDim.x * blockDim.x;
    if (i < NE) g_count[i] = 0;
    for (; i < n; i += stride) out[i] = 0.0f;
}

// ---------------- gating: logits, softmax, top-2, routing ----------------
__global__ __launch_bounds__(256) void gating_kernel(const float* __restrict__ x,
                                                     const float* __restrict__ gw) {
    __shared__ float sgw[NE * H];  // 32KB
    for (int i = threadIdx.x; i < NE * H; i += blockDim.x) sgw[i] = gw[i];
    __syncthreads();

    int warp = threadIdx.x >> 5, lane = threadIdx.x & 31;
    int t = blockIdx.x * 8 + warp;
    const float* xr = x + (size_t)t * H;

    float acc[NE];
#pragma unroll
    for (int e = 0; e < NE; e++) acc[e] = 0.0f;
    for (int k = lane; k < H; k += 32) {
        float xv = xr[k];
#pragma unroll
        for (int e = 0; e < NE; e++) acc[e] += xv * sgw[e * H + k];
    }
#pragma unroll
    for (int e = 0; e < NE; e++) {
#pragma unroll
        for (int off = 16; off; off >>= 1)
            acc[e] += __shfl_xor_sync(0xffffffffu, acc[e], off);
    }

    if (lane == 0) {
        float mx = acc[0];
#pragma unroll
        for (int e = 1; e < NE; e++) mx = fmaxf(mx, acc[e]);
        float p[NE], s = 0.0f;
#pragma unroll
        for (int e = 0; e < NE; e++) { p[e] = expf(acc[e] - mx); s += p[e]; }
        float inv = 1.0f / s;
#pragma unroll
        for (int e = 0; e < NE; e++) { p[e] *= inv; g_probs[t * NE + e] = p[e]; }

        int b0 = 0;
#pragma unroll
        for (int e = 1; e < NE; e++) if (p[e] > p[b0]) b0 = e;
        int b1 = (b0 == 0) ? 1 : 0;
#pragma unroll
        for (int e = 0; e < NE; e++) if (e != b0 && p[e] > p[b1]) b1 = e;

        float d = 1.0f / (p[b0] + p[b1] + 1e-9f);
        int pos0 = atomicAdd(&g_count[b0], 1);
        g_tok[b0 * T_TOK + pos0] = t;
        g_wt[b0 * T_TOK + pos0] = p[b0] * d;
        int pos1 = atomicAdd(&g_count[b1], 1);
        g_tok[b1 * T_TOK + pos1] = t;
        g_wt[b1 * T_TOK + pos1] = p[b1] * d;
    }
}

// ---------------- prefix scan + aux loss (deterministic reduction) ----------------
__global__ void scan_aux_kernel(float* out) {
    __shared__ float red[256];
    __shared__ float imp[NE];
    float s[NE];
#pragma unroll
    for (int e = 0; e < NE; e++) s[e] = 0.0f;
    for (int i = threadIdx.x; i < T_TOK; i += 256) {
#pragma unroll
        for (int e = 0; e < NE; e++) s[e] += g_probs[i * NE + e];
    }
    for (int e = 0; e < NE; e++) {
        red[threadIdx.x] = s[e];
        __syncthreads();
        for (int off = 128; off; off >>= 1) {
            if (threadIdx.x < off) red[threadIdx.x] += red[threadIdx.x + off];
            __syncthreads();
        }
        if (threadIdx.x == 0) imp[e] = red[0];
        __syncthreads();
    }
    if (threadIdx.x == 0) {
        int b = 0;
        float aux = 0.0f;
        for (int e = 0; e < NE; e++) {
            g_base[e] = b;
            b += g_count[e];
            float usage = (float)g_count[e] / ((float)(T_TOK * 2) + 1e-9f);
            float importance = imp[e] / (float)T_TOK;
            aux += usage * importance;
        }
        aux = fminf(aux * (float)NE * 0.01f, 1.0f);
        out[(size_t)T_TOK * H] = aux;
    }
}

// ---------------- GEMM1: h = silu(x@Wg^T) * (x@Wu^T), tf32 tensor cores ----------------
#define BM1 128
#define BN1 64
#define BK 32
#define KSTR (BK + 4)  // 36, conflict-free for frag access & 16B-aligned rows

__global__ __launch_bounds__(256, 1) void gemm1_kernel(const float* __restrict__ x,
                                                       const float* __restrict__ w1) {
    int e = blockIdx.z;
    int cnt = g_count[e];
    int m0 = blockIdx.x * BM1;
    if (m0 >= cnt) return;
    int n0 = blockIdx.y * BN1;

    __shared__ __align__(16) float smem[BM1 * KSTR + 2 * BN1 * KSTR];  // 36KB
    float* As = smem;
    float* Bg = smem + BM1 * KSTR;
    float* Bu = Bg + BN1 * KSTR;

    int tid = threadIdx.x, warp = tid >> 5, lane = tid & 31;
    int g4 = lane >> 2, tig = lane & 3;
    int wm = warp >> 1, wn = warp & 1;

    const float* Wg = w1 + (size_t)e * 2 * IDIM * H + (size_t)n0 * H;
    const float* Wu = Wg + (size_t)IDIM * H;

    // A load plan: 128 rows x 8 float4 = 1024 f4 -> 4 per thread (gathered rows)
    const float* aptr[4];
#pragma unroll
    for (int t = 0; t < 4; t++) {
        int idx = tid + t * 256;
        int r = idx >> 3, c = idx & 7;
        int tok = (m0 + r < cnt) ? g_tok[e * T_TOK + m0 + r] : -1;
        aptr[t] = (tok >= 0) ? x + (size_t)tok * H + c * 4 : nullptr;
    }

    float4 ra[4], rbg[2], rbu[2];

    // prologue load k=0
#pragma unroll
    for (int t = 0; t < 4; t++)
        ra[t] = aptr[t] ? *(const float4*)(aptr[t]) : make_float4(0, 0, 0, 0);
#pragma unroll
    for (int t = 0; t < 2; t++) {
        int idx = tid + t * 256;
        int r = idx >> 3, c = idx & 7;
        rbg[t] = *(const float4*)(Wg + (size_t)r * H + c * 4);
        rbu[t] = *(const float4*)(Wu + (size_t)r * H + c * 4);
    }
    // store to smem (tf32-rounded)
#pragma unroll
    for (int t = 0; t < 4; t++) {
        int idx = tid + t * 256;
        int r = idx >> 3, c = idx & 7;
        uint4 v = {tf32b(ra[t].x), tf32b(ra[t].y), tf32b(ra[t].z), tf32b(ra[t].w)};
        *(uint4*)&As[r * KSTR + c * 4] = v;
    }
#pragma unroll
    for (int t = 0; t < 2; t++) {
        int idx = tid + t * 256;
        int r = idx >> 3, c = idx & 7;
        uint4 vg = {tf32b(rbg[t].x), tf32b(rbg[t].y), tf32b(rbg[t].z), tf32b(rbg[t].w)};
        *(uint4*)&Bg[r * KSTR + c * 4] = vg;
        uint4 vu = {tf32b(rbu[t].x), tf32b(rbu[t].y), tf32b(rbu[t].z), tf32b(rbu[t].w)};
        *(uint4*)&Bu[r * KSTR + c * 4] = vu;
    }
    __syncthreads();

    float accg[2][4][4], accu[2][4][4];
#pragma unroll
    for (int a = 0; a < 2; a++)
#pragma unroll
        for (int b = 0; b < 4; b++)
#pragma unroll
            for (int c = 0; c < 4; c++) { accg[a][b][c] = 0.0f; accu[a][b][c] = 0.0f; }

    const int NKT = H / BK;  // 32
    for (int kt = 0; kt < NKT; kt++) {
        if (kt + 1 < NKT) {
            int k0 = (kt + 1) * BK;
#pragma unroll
            for (int t = 0; t < 4; t++)
                ra[t] = aptr[t] ? *(const float4*)(aptr[t] + k0) : make_float4(0, 0, 0, 0);
#pragma unroll
            for (int t = 0; t < 2; t++) {
                int idx = tid + t * 256;
                int r = idx >> 3, c = idx & 7;
                rbg[t] = *(const float4*)(Wg + (size_t)r * H + k0 + c * 4);
                rbu[t] = *(const float4*)(Wu + (size_t)r * H + k0 + c * 4);
            }
        }
#pragma unroll
        for (int ks = 0; ks < 4; ks++) {
            int kk = ks * 8;
            unsigned a[2][4];
#pragma unroll
            for (int mf = 0; mf < 2; mf++) {
                int r = wm * 32 + mf * 16;
                a[mf][0] = __float_as_uint(As[(r + g4) * KSTR + kk + tig]);
                a[mf][1] = __float_as_uint(As[(r + g4 + 8) * KSTR + kk + tig]);
                a[mf][2] = __float_as_uint(As[(r + g4) * KSTR + kk + tig + 4]);
                a[mf][3] = __float_as_uint(As[(r + g4 + 8) * KSTR + kk + tig + 4]);
            }
            unsigned bg[4][2], bu[4][2];
#pragma unroll
            for (int nf = 0; nf < 4; nf++) {
                int c = wn * 32 + nf * 8 + g4;
                bg[nf][0] = __float_as_uint(Bg[c * KSTR + kk + tig]);
                bg[nf][1] = __float_as_uint(Bg[c * KSTR + kk + tig + 4]);
                bu[nf][0] = __float_as_uint(Bu[c * KSTR + kk + tig]);
                bu[nf][1] = __float_as_uint(Bu[c * KSTR + kk + tig + 4]);
            }
#pragma unroll
            for (int mf = 0; mf < 2; mf++)
#pragma unroll
                for (int nf = 0; nf < 4; nf++) {
                    mma_tf32(accg[mf][nf], a[mf], bg[nf]);
                    mma_tf32(accu[mf][nf], a[mf], bu[nf]);
                }
        }
        __syncthreads();
        if (kt + 1 < NKT) {
#pragma unroll
            for (int t = 0; t < 4; t++) {
                int idx = tid + t * 256;
                int r = idx >> 3, c = idx & 7;
                uint4 v = {tf32b(ra[t].x), tf32b(ra[t].y), tf32b(ra[t].z), tf32b(ra[t].w)};
                *(uint4*)&As[r * KSTR + c * 4] = v;
            }
#pragma unroll
            for (int t = 0; t < 2; t++) {
                int idx = tid + t * 256;
                int r = idx >> 3, c = idx & 7;
                uint4 vg = {tf32b(rbg[t].x), tf32b(rbg[t].y), tf32b(rbg[t].z), tf32b(rbg[t].w)};
                *(uint4*)&Bg[r * KSTR + c * 4] = vg;
                uint4 vu = {tf32b(rbu[t].x), tf32b(rbu[t].y), tf32b(rbu[t].z), tf32b(rbu[t].w)};
                *(uint4*)&Bu[r * KSTR + c * 4] = vu;
            }
            __syncthreads();
        }
    }

    // epilogue: h = silu(g)*u, stage through smem (stride 68 => aligned + low conflict)
    __syncthreads();
    float* Hs = smem;  // 128*68 = 8704 floats <= 9216
#pragma unroll
    for (int mf = 0; mf < 2; mf++)
#pragma unroll
        for (int nf = 0; nf < 4; nf++)
#pragma unroll
            for (int i = 0; i < 4; i++) {
                int row = wm * 32 + mf * 16 + g4 + ((i >= 2) ? 8 : 0);
                int col = wn * 32 + nf * 8 + tig * 2 + (i & 1);
                float gv = accg[mf][nf][i], uv = accu[mf][nf][i];
                float sv = gv / (1.0f + __expf(-gv));
                Hs[row * 68 + col] = sv * uv;
            }
    __syncthreads();

    int mybase = g_base[e];
#pragma unroll
    for (int t = 0; t < 8; t++) {
        int idx = tid + t * 256;
        int r = idx >> 4, c4 = idx & 15;
        if (m0 + r < cnt) {
            float4 v = *(float4*)&Hs[r * 68 + c4 * 4];
            uint4 o = {tf32b(v.x), tf32b(v.y), tf32b(v.z), tf32b(v.w)};
            *(uint4*)&g_h[(size_t)(mybase + m0 + r) * IDIM + n0 + c4 * 4] = o;
        }
    }
}

// ---------------- GEMM2: out[tok] += w * (h @ W2^T) ----------------
#define BM2 128
#define BN2 128

__global__ __launch_bounds__(256, 1) void gemm2_kernel(const float* __restrict__ w2,
                                                       float* __restrict__ out) {
    int e = blockIdx.z;
    int cnt = g_count[e];
    int m0 = blockIdx.x * BM2;
    if (m0 >= cnt) return;
    int n0 = blockIdx.y * BN2;
    int base = g_base[e];

    __shared__ __align__(16) float As[BM2 * KSTR];  // 18KB
    __shared__ __align__(16) float Bs[BN2 * KSTR];  // 18KB

    int tid = threadIdx.x, warp = tid >> 5, lane = tid & 31;
    int g4 = lane >> 2, tig = lane & 3;
    int wm = warp >> 1, wn = warp & 1;

    const float* Ab = g_h + (size_t)(base + m0) * IDIM;
    const float* W = w2 + (size_t)e * H * IDIM + (size_t)n0 * IDIM;

    float4 raa[4], rbb[4];
    // prologue
#pragma unroll
    for (int t = 0; t < 4; t++) {
        int idx = tid + t * 256;
        int r = idx >> 3, c = idx & 7;
        raa[t] = *(const float4*)(Ab + (size_t)r * IDIM + c * 4);
        rbb[t] = *(const float4*)(W + (size_t)r * IDIM + c * 4);
    }
#pragma unroll
    for (int t = 0; t < 4; t++) {
        int idx = tid + t * 256;
        int r = idx >> 3, c = idx & 7;
        *(float4*)&As[r * KSTR + c * 4] = raa[t];  // already tf32-rounded
        uint4 v = {tf32b(rbb[t].x), tf32b(rbb[t].y), tf32b(rbb[t].z), tf32b(rbb[t].w)};
        *(uint4*)&Bs[r * KSTR + c * 4] = v;
    }
    __syncthreads();

    float acc[2][8][4];
#pragma unroll
    for (int a = 0; a < 2; a++)
#pragma unroll
        for (int b = 0; b < 8; b++)
#pragma unroll
            for (int c = 0; c < 4; c++) acc[a][b][c] = 0.0f;

    const int NKT = IDIM / BK;  // 128
    for (int kt = 0; kt < NKT; kt++) {
        if (kt + 1 < NKT) {
            int k0 = (kt + 1) * BK;
#pragma unroll
            for (int t = 0; t < 4; t++) {
                int idx = tid + t * 256;
                int r = idx >> 3, c = idx & 7;
                raa[t] = *(const float4*)(Ab + (size_t)r * IDIM + k0 + c * 4);
                rbb[t] = *(const float4*)(W + (size_t)r * IDIM + k0 + c * 4);
            }
        }
#pragma unroll
        for (int ks = 0; ks < 4; ks++) {
            int kk = ks * 8;
            unsigned a[2][4];
#pragma unroll
            for (int mf = 0; mf < 2; mf++) {
                int r = wm * 32 + mf * 16;
                a[mf][0] = __float_as_uint(As[(r + g4) * KSTR + kk + tig]);
                a[mf][1] = __float_as_uint(As[(r + g4 + 8) * KSTR + kk + tig]);
                a[mf][2] = __float_as_uint(As[(r + g4) * KSTR + kk + tig + 4]);
                a[mf][3] = __float_as_uint(As[(r + g4 + 8) * KSTR + kk + tig + 4]);
            }
            unsigned b[8][2];
#pragma unroll
            for (int nf = 0; nf < 8; nf++) {
                int c = wn * 64 + nf * 8 + g4;
                b[nf][0] = __float_as_uint(Bs[c * KSTR + kk + tig]);
                b[nf][1] = __float_as_uint(Bs[c * KSTR + kk + tig + 4]);
            }
#pragma unroll
            for (int mf = 0; mf < 2; mf++)
#pragma unroll
                for (int nf = 0; nf < 8; nf++) mma_tf32(acc[mf][nf], a[mf], b[nf]);
        }
        __syncthreads();
        if (kt + 1 < NKT) {
#pragma unroll
            for (int t = 0; t < 4; t++) {
                int idx = tid + t * 256;
                int r = idx >> 3, c = idx & 7;
                *(float4*)&As[r * KSTR + c * 4] = raa[t];
                uint4 v = {tf32b(rbb[t].x), tf32b(rbb[t].y), tf32b(rbb[t].z), tf32b(rbb[t].w)};
                *(uint4*)&Bs[r * KSTR + c * 4] = v;
            }
            __syncthreads();
        }
    }

    // epilogue: weighted scatter-add (exactly 2 adds per out element -> deterministic)
#pragma unroll
    for (int mf = 0; mf < 2; mf++) {
#pragma unroll
        for (int half = 0; half < 2; half++) {
            int r = wm * 32 + mf * 16 + g4 + half * 8;
            int gr = m0 + r;
            if (gr < cnt) {
                int tok = g_tok[e * T_TOK + gr];
                float w = g_wt[e * T_TOK + gr];
                float* op = out + (size_t)tok * H + n0 + wn * 64;
#pragma unroll
                for (int nf = 0; nf < 8; nf++) {
                    atomicAdd(op + nf * 8 + tig * 2, w * acc[mf][nf][half * 2 + 0]);
                    atomicAdd(op + nf * 8 + tig * 2 + 1, w * acc[mf][nf][half * 2 + 1]);
                }
            }
        }
    }
}

// ---------------- launch ----------------
extern "C" void kernel_launch(void* const* d_in, const int* in_sizes, int n_in,
                              void* d_out, int out_size) {
    const float* x = (const float*)d_in[0];
    const float* gate_w = (const float*)d_in[1];
    const float* gate_up_w = (const float*)d_in[2];
    const float* down_w = (const float*)d_in[3];
    float* out = (float*)d_out;

    zero_out_kernel<<<4096, 256>>>(out, out_size);
    gating_kernel<<<T_TOK / 8, 256>>>(x, gate_w);
    scan_aux_kernel<<<1, 256>>>(out);

    dim3 g1(T_TOK / BM1, IDIM / BN1, NE);  // (64, 64, 8)
    gemm1_kernel<<<g1, 256>>>(x, gate_up_w);

    dim3 g2(T_TOK / BM2, H / BN2, NE);  // (64, 8, 8)
    gemm2_kernel<<<g2, 256>>>(down_w, out);
}

// round 6
// speedup vs baseline: 1.8211x; 1.1638x over previous
#include <cuda_runtime.h>
#include <cuda_fp16.h>
#include <cstdint>
#include <math.h>

#define H 1024
#define IDIM 4096
#define NE 8
#define T_TOK 8192
#define NSLOT (2 * T_TOK)

// ---------------- device scratch ----------------
__device__ int    g_count[NE];
__device__ int    g_base[NE];
__device__ int    g_tok[NE * T_TOK];
__device__ float  g_wt[NE * T_TOK];
__device__ float  g_probs[T_TOK * NE];
// fp16 hidden activations, +128 pad rows so GEMM2 tiles may over-read
__device__ __half g_h[(size_t)(NSLOT + 128) * IDIM];

// ---------------- helpers ----------------
__device__ __forceinline__ uint32_t h2pack(float a, float b) {
    __half2 h = __floats2half2_rn(a, b);
    return *(uint32_t*)&h;
}
__device__ __forceinline__ uint2 cvt4h(float4 v) {
    return make_uint2(h2pack(v.x, v.y), h2pack(v.z, v.w));
}

__device__ __forceinline__ void mma_f16(float* d, const unsigned* a, const unsigned* b) {
    asm volatile(
        "mma.sync.aligned.m16n8k16.row.col.f32.f16.f16.f32 "
        "{%0,%1,%2,%3}, {%4,%5,%6,%7}, {%8,%9}, {%0,%1,%2,%3};\n"
        : "+f"(d[0]), "+f"(d[1]), "+f"(d[2]), "+f"(d[3])
        : "r"(a[0]), "r"(a[1]), "r"(a[2]), "r"(a[3]), "r"(b[0]), "r"(b[1]));
}

// ---------------- zero / init ----------------
__global__ void zero_out_kernel(float* out, int n) {
    int i = blockIdx.x * blockDim.x + threadIdx.x;
    int stride = gridDim.x * blockDim.x;
    if (i < NE) g_count[i] = 0;
    for (; i < n; i += stride) out[i] = 0.0f;
}

// ---------------- gating: logits, softmax, top-2, routing ----------------
__global__ __launch_bounds__(256) void gating_kernel(const float* __restrict__ x,
                                                     const float* __restrict__ gw) {
    __shared__ float sgw[NE * H];
    for (int i = threadIdx.x; i < NE * H; i += blockDim.x) sgw[i] = gw[i];
    __syncthreads();

    int warp = threadIdx.x >> 5, lane = threadIdx.x & 31;
    int t = blockIdx.x * 8 + warp;
    const float* xr = x + (size_t)t * H;

    float acc[NE];
#pragma unroll
    for (int e = 0; e < NE; e++) acc[e] = 0.0f;
    for (int k = lane; k < H; k += 32) {
        float xv = xr[k];
#pragma unroll
        for (int e = 0; e < NE; e++) acc[e] += xv * sgw[e * H + k];
    }
#pragma unroll
    for (int e = 0; e < NE; e++)
#pragma unroll
        for (int off = 16; off; off >>= 1)
            acc[e] += __shfl_xor_sync(0xffffffffu, acc[e], off);

    if (lane == 0) {
        float mx = acc[0];
#pragma unroll
        for (int e = 1; e < NE; e++) mx = fmaxf(mx, acc[e]);
        float p[NE], s = 0.0f;
#pragma unroll
        for (int e = 0; e < NE; e++) { p[e] = expf(acc[e] - mx); s += p[e]; }
        float inv = 1.0f / s;
#pragma unroll
        for (int e = 0; e < NE; e++) { p[e] *= inv; g_probs[t * NE + e] = p[e]; }

        int b0 = 0;
#pragma unroll
        for (int e = 1; e < NE; e++) if (p[e] > p[b0]) b0 = e;
        int b1 = (b0 == 0) ? 1 : 0;
#pragma unroll
        for (int e = 0; e < NE; e++) if (e != b0 && p[e] > p[b1]) b1 = e;

        float d = 1.0f / (p[b0] + p[b1] + 1e-9f);
        int pos0 = atomicAdd(&g_count[b0], 1);
        g_tok[b0 * T_TOK + pos0] = t;
        g_wt[b0 * T_TOK + pos0] = p[b0] * d;
        int pos1 = atomicAdd(&g_count[b1], 1);
        g_tok[b1 * T_TOK + pos1] = t;
        g_wt[b1 * T_TOK + pos1] = p[b1] * d;
    }
}

// ---------------- prefix scan + aux loss ----------------
__global__ void scan_aux_kernel(float* out) {
    __shared__ float red[256];
    __shared__ float imp[NE];
    float s[NE];
#pragma unroll
    for (int e = 0; e < NE; e++) s[e] = 0.0f;
    for (int i = threadIdx.x; i < T_TOK; i += 256)
#pragma unroll
        for (int e = 0; e < NE; e++) s[e] += g_probs[i * NE + e];
    for (int e = 0; e < NE; e++) {
        red[threadIdx.x] = s[e];
        __syncthreads();
        for (int off = 128; off; off >>= 1) {
            if (threadIdx.x < off) red[threadIdx.x] += red[threadIdx.x + off];
            __syncthreads();
        }
        if (threadIdx.x == 0) imp[e] = red[0];
        __syncthreads();
    }
    if (threadIdx.x == 0) {
        int b = 0;
        float aux = 0.0f;
        for (int e = 0; e < NE; e++) {
            g_base[e] = b;
            b += g_count[e];
            float usage = (float)g_count[e] / ((float)(T_TOK * 2) + 1e-9f);
            aux += usage * (imp[e] / (float)T_TOK);
        }
        out[(size_t)T_TOK * H] = fminf(aux * (float)NE * 0.01f, 1.0f);
    }
}

// ---------------- GEMM tiling (fp16 operands, fp32 accum) ----------------
#define BK 32
#define KS2 40    // half stride per smem row
#define KS2W 20   // b32 words per smem row

// ---------------- GEMM1: h = silu(x@Wg^T) * (x@Wu^T) ----------------
#define BM1 128
#define BN1 64

__global__ __launch_bounds__(256, 1) void gemm1_kernel(const float* __restrict__ x,
                                                       const float* __restrict__ w1) {
    int e = blockIdx.z;
    int cnt = g_count[e];
    int m0 = blockIdx.x * BM1;
    if (m0 >= cnt) return;
    int n0 = blockIdx.y * BN1;

    __shared__ __align__(16) __half sm[(BM1 + 2 * BN1) * KS2];  // 20480 B
    __half* As = sm;
    __half* Bg = sm + BM1 * KS2;
    __half* Bu = Bg + BN1 * KS2;
    uint32_t* As32 = (uint32_t*)As;
    uint32_t* Bg32 = (uint32_t*)Bg;
    uint32_t* Bu32 = (uint32_t*)Bu;

    int tid = threadIdx.x, warp = tid >> 5, lane = tid & 31;
    int g4 = lane >> 2, tig = lane & 3;
    int wm = warp >> 1, wn = warp & 1;

    const float* Wg = w1 + (size_t)e * 2 * IDIM * H + (size_t)n0 * H;
    const float* Wu = Wg + (size_t)IDIM * H;

    const float* aptr[4];
#pragma unroll
    for (int t = 0; t < 4; t++) {
        int idx = tid + t * 256;
        int r = idx >> 3, c4 = idx & 7;
        int tok = (m0 + r < cnt) ? g_tok[e * T_TOK + m0 + r] : -1;
        aptr[t] = (tok >= 0) ? x + (size_t)tok * H + c4 * 4 : nullptr;
    }

    float4 ra[4], rbg[2], rbu[2];
#pragma unroll
    for (int t = 0; t < 4; t++)
        ra[t] = aptr[t] ? *(const float4*)(aptr[t]) : make_float4(0, 0, 0, 0);
#pragma unroll
    for (int t = 0; t < 2; t++) {
        int idx = tid + t * 256;
        int r = idx >> 3, c4 = idx & 7;
        rbg[t] = *(const float4*)(Wg + (size_t)r * H + c4 * 4);
        rbu[t] = *(const float4*)(Wu + (size_t)r * H + c4 * 4);
    }
#pragma unroll
    for (int t = 0; t < 4; t++) {
        int idx = tid + t * 256;
        int r = idx >> 3, c4 = idx & 7;
        *(uint2*)&As[r * KS2 + c4 * 4] = cvt4h(ra[t]);
    }
#pragma unroll
    for (int t = 0; t < 2; t++) {
        int idx = tid + t * 256;
        int r = idx >> 3, c4 = idx & 7;
        *(uint2*)&Bg[r * KS2 + c4 * 4] = cvt4h(rbg[t]);
        *(uint2*)&Bu[r * KS2 + c4 * 4] = cvt4h(rbu[t]);
    }
    __syncthreads();

    float accg[2][4][4], accu[2][4][4];
#pragma unroll
    for (int a = 0; a < 2; a++)
#pragma unroll
        for (int b = 0; b < 4; b++)
#pragma unroll
            for (int c = 0; c < 4; c++) { accg[a][b][c] = 0.0f; accu[a][b][c] = 0.0f; }

    const int NKT = H / BK;  // 32
    for (int kt = 0; kt < NKT; kt++) {
        if (kt + 1 < NKT) {
            int k0 = (kt + 1) * BK;
#pragma unroll
            for (int t = 0; t < 4; t++)
                ra[t] = aptr[t] ? *(const float4*)(aptr[t] + k0) : make_float4(0, 0, 0, 0);
#pragma unroll
            for (int t = 0; t < 2; t++) {
                int idx = tid + t * 256;
                int r = idx >> 3, c4 = idx & 7;
                rbg[t] = *(const float4*)(Wg + (size_t)r * H + k0 + c4 * 4);
                rbu[t] = *(const float4*)(Wu + (size_t)r * H + k0 + c4 * 4);
            }
        }
#pragma unroll
        for (int ks = 0; ks < 2; ks++) {
            int kw = ks * 8;  // b32 word offset of this k16 step
            unsigned a[2][4];
#pragma unroll
            for (int mf = 0; mf < 2; mf++) {
                int r = wm * 32 + mf * 16;
                int w0 = (r + g4) * KS2W + kw + tig;
                int w1r = (r + g4 + 8) * KS2W + kw + tig;
                a[mf][0] = As32[w0];
                a[mf][1] = As32[w1r];
                a[mf][2] = As32[w0 + 4];
                a[mf][3] = As32[w1r + 4];
            }
            unsigned bg[4][2], bu[4][2];
#pragma unroll
            for (int nf = 0; nf < 4; nf++) {
                int c = wn * 32 + nf * 8 + g4;
                int w0 = c * KS2W + kw + tig;
                bg[nf][0] = Bg32[w0];
                bg[nf][1] = Bg32[w0 + 4];
                bu[nf][0] = Bu32[w0];
                bu[nf][1] = Bu32[w0 + 4];
            }
#pragma unroll
            for (int mf = 0; mf < 2; mf++)
#pragma unroll
                for (int nf = 0; nf < 4; nf++) {
                    mma_f16(accg[mf][nf], a[mf], bg[nf]);
                    mma_f16(accu[mf][nf], a[mf], bu[nf]);
                }
        }
        __syncthreads();
        if (kt + 1 < NKT) {
#pragma unroll
            for (int t = 0; t < 4; t++) {
                int idx = tid + t * 256;
                int r = idx >> 3, c4 = idx & 7;
                *(uint2*)&As[r * KS2 + c4 * 4] = cvt4h(ra[t]);
            }
#pragma unroll
            for (int t = 0; t < 2; t++) {
                int idx = tid + t * 256;
                int r = idx >> 3, c4 = idx & 7;
                *(uint2*)&Bg[r * KS2 + c4 * 4] = cvt4h(rbg[t]);
                *(uint2*)&Bu[r * KS2 + c4 * 4] = cvt4h(rbu[t]);
            }
            __syncthreads();
        }
    }

    // epilogue: silu(g)*u -> fp16, stage through smem (stride 72 halves)
    __syncthreads();
    __half* Hs = sm;  // 128*72 = 9216 halves <= 10240
#pragma unroll
    for (int mf = 0; mf < 2; mf++)
#pragma unroll
        for (int nf = 0; nf < 4; nf++)
#pragma unroll
            for (int hh = 0; hh < 2; hh++) {
                int row = wm * 32 + mf * 16 + g4 + hh * 8;
                int col = wn * 32 + nf * 8 + tig * 2;
                float gv0 = accg[mf][nf][hh * 2 + 0], uv0 = accu[mf][nf][hh * 2 + 0];
                float gv1 = accg[mf][nf][hh * 2 + 1], uv1 = accu[mf][nf][hh * 2 + 1];
                float h0 = gv0 / (1.0f + __expf(-gv0)) * uv0;
                float h1 = gv1 / (1.0f + __expf(-gv1)) * uv1;
                *(uint32_t*)&Hs[row * 72 + col] = h2pack(h0, h1);
            }
    __syncthreads();

    // write: 128 rows x 64 halves = 128 x 8 uint4 chunks = 1024 chunks
    int mybase = g_base[e];
#pragma unroll
    for (int t = 0; t < 4; t++) {
        int idx = tid + t * 256;
        int r = idx >> 3, c8 = idx & 7;
        if (m0 + r < cnt) {
            uint4 v = *(uint4*)&Hs[r * 72 + c8 * 8];
            *(uint4*)&g_h[(size_t)(mybase + m0 + r) * IDIM + n0 + c8 * 8] = v;
        }
    }
}

// ---------------- GEMM2: out[tok] += w * (h @ W2^T) ----------------
#define BM2 128
#define BN2 128

__global__ __launch_bounds__(256, 1) void gemm2_kernel(const float* __restrict__ w2,
                                                       float* __restrict__ out) {
    int e = blockIdx.z;
    int cnt = g_count[e];
    int m0 = blockIdx.x * BM2;
    if (m0 >= cnt) return;
    int n0 = blockIdx.y * BN2;
    int base = g_base[e];

    __shared__ __align__(16) __half Ash[BM2 * KS2];  // 10240 B
    __shared__ __align__(16) __half Bsh[BN2 * KS2];  // 10240 B
    uint32_t* As32 = (uint32_t*)Ash;
    uint32_t* Bs32 = (uint32_t*)Bsh;

    int tid = threadIdx.x, warp = tid >> 5, lane = tid & 31;
    int g4 = lane >> 2, tig = lane & 3;
    int wm = warp >> 1, wn = warp & 1;

    const __half* Ab = g_h + (size_t)(base + m0) * IDIM;
    const float* W = w2 + (size_t)e * H * IDIM + (size_t)n0 * IDIM;

    uint4 raa[2];
    float4 rbb[4];
#pragma unroll
    for (int t = 0; t < 2; t++) {
        int idx = tid + t * 256;
        int r = idx >> 2, c16 = idx & 3;
        raa[t] = *(const uint4*)(Ab + (size_t)r * IDIM + c16 * 8);
    }
#pragma unroll
    for (int t = 0; t < 4; t++) {
        int idx = tid + t * 256;
        int r = idx >> 3, c4 = idx & 7;
        rbb[t] = *(const float4*)(W + (size_t)r * IDIM + c4 * 4);
    }
#pragma unroll
    for (int t = 0; t < 2; t++) {
        int idx = tid + t * 256;
        int r = idx >> 2, c16 = idx & 3;
        *(uint4*)&Ash[r * KS2 + c16 * 8] = raa[t];
    }
#pragma unroll
    for (int t = 0; t < 4; t++) {
        int idx = tid + t * 256;
        int r = idx >> 3, c4 = idx & 7;
        *(uint2*)&Bsh[r * KS2 + c4 * 4] = cvt4h(rbb[t]);
    }
    __syncthreads();

    float acc[2][8][4];
#pragma unroll
    for (int a = 0; a < 2; a++)
#pragma unroll
        for (int b = 0; b < 8; b++)
#pragma unroll
            for (int c = 0; c < 4; c++) acc[a][b][c] = 0.0f;

    const int NKT = IDIM / BK;  // 128
    for (int kt = 0; kt < NKT; kt++) {
        if (kt + 1 < NKT) {
            int k0 = (kt + 1) * BK;
#pragma unroll
            for (int t = 0; t < 2; t++) {
                int idx = tid + t * 256;
                int r = idx >> 2, c16 = idx & 3;
                raa[t] = *(const uint4*)(Ab + (size_t)r * IDIM + k0 + c16 * 8);
            }
#pragma unroll
            for (int t = 0; t < 4; t++) {
                int idx = tid + t * 256;
                int r = idx >> 3, c4 = idx & 7;
                rbb[t] = *(const float4*)(W + (size_t)r * IDIM + k0 + c4 * 4);
            }
        }
#pragma unroll
        for (int ks = 0; ks < 2; ks++) {
            int kw = ks * 8;
            unsigned a[2][4];
#pragma unroll
            for (int mf = 0; mf < 2; mf++) {
                int r = wm * 32 + mf * 16;
                int w0 = (r + g4) * KS2W + kw + tig;
                int w1r = (r + g4 + 8) * KS2W + kw + tig;
                a[mf][0] = As32[w0];
                a[mf][1] = As32[w1r];
                a[mf][2] = As32[w0 + 4];
                a[mf][3] = As32[w1r + 4];
            }
            unsigned b[8][2];
#pragma unroll
            for (int nf = 0; nf < 8; nf++) {
                int c = wn * 64 + nf * 8 + g4;
                int w0 = c * KS2W + kw + tig;
                b[nf][0] = Bs32[w0];
                b[nf][1] = Bs32[w0 + 4];
            }
#pragma unroll
            for (int mf = 0; mf < 2; mf++)
#pragma unroll
                for (int nf = 0; nf < 8; nf++) mma_f16(acc[mf][nf], a[mf], b[nf]);
        }
        __syncthreads();
        if (kt + 1 < NKT) {
#pragma unroll
            for (int t = 0; t < 2; t++) {
                int idx = tid + t * 256;
                int r = idx >> 2, c16 = idx & 3;
                *(uint4*)&Ash[r * KS2 + c16 * 8] = raa[t];
            }
#pragma unroll
            for (int t = 0; t < 4; t++) {
                int idx = tid + t * 256;
                int r = idx >> 3, c4 = idx & 7;
                *(uint2*)&Bsh[r * KS2 + c4 * 4] = cvt4h(rbb[t]);
            }
            __syncthreads();
        }
    }

    // epilogue: weighted scatter-add (exactly 2 adds per out element)
#pragma unroll
    for (int mf = 0; mf < 2; mf++) {
#pragma unroll
        for (int half = 0; half < 2; half++) {
            int r = wm * 32 + mf * 16 + g4 + half * 8;
            int gr = m0 + r;
            if (gr < cnt) {
                int tok = g_tok[e * T_TOK + gr];
                float w = g_wt[e * T_TOK + gr];
                float* op = out + (size_t)tok * H + n0 + wn * 64;
#pragma unroll
                for (int nf = 0; nf < 8; nf++) {
                    atomicAdd(op + nf * 8 + tig * 2, w * acc[mf][nf][half * 2 + 0]);
                    atomicAdd(op + nf * 8 + tig * 2 + 1, w * acc[mf][nf][half * 2 + 1]);
                }
            }
        }
    }
}

// ---------------- launch ----------------
extern "C" void kernel_launch(void* const* d_in, const int* in_sizes, int n_in,
                              void* d_out, int out_size) {
    const float* x = (const float*)d_in[0];
    const float* gate_w = (const float*)d_in[1];
    const float* gate_up_w = (const float*)d_in[2];
    const float* down_w = (const float*)d_in[3];
    float* out = (float*)d_out;

    zero_out_kernel<<<4096, 256>>>(out, out_size);
    gating_kernel<<<T_TOK / 8, 256>>>(x, gate_w);
    scan_aux_kernel<<<1, 256>>>(out);

    dim3 g1(T_TOK / BM1, IDIM / BN1, NE);  // (64, 64, 8)
    gemm1_kernel<<<g1, 256>>>(x, gate_up_w);

    dim3 g2(T_TOK / BM2, H / BN2, NE);     // (64, 8, 8)
    gemm2_kernel<<<g2, 256>>>(down_w, out);
}

// round 10
// speedup vs baseline: 3.0415x; 1.6702x over previous
#include <cuda_runtime.h>
#include <cuda_fp16.h>
#include <cstdint>
#include <math.h>

#define H 1024
#define IDIM 4096
#define NE 8
#define T_TOK 8192
#define NSLOT (2 * T_TOK)

// ---------------- device scratch ----------------
__device__ int    g_count[NE];
__device__ int    g_base[NE];
__device__ int    g_tok[NE * T_TOK];
__device__ float  g_wt[NE * T_TOK];
__device__ float  g_probs[T_TOK * NE];
__device__ __half g_h[(size_t)(NSLOT + 128) * IDIM];     // hidden acts (fp16)
__device__ __half g_xh[(size_t)T_TOK * H];               // x in fp16
__device__ __half g_w1h[(size_t)NE * 2 * IDIM * H];      // gate_up_w fp16
__device__ __half g_w2h[(size_t)NE * H * IDIM];          // down_w fp16

// ---------------- helpers ----------------
__device__ __forceinline__ uint32_t h2pack(float a, float b) {
    __half2 h = __floats2half2_rn(a, b);
    return *(uint32_t*)&h;
}
__device__ __forceinline__ uint2 cvt4h(float4 v) {
    return make_uint2(h2pack(v.x, v.y), h2pack(v.z, v.w));
}
__device__ __forceinline__ uint32_t smem_u32(const void* p) {
    uint32_t a;
    asm("{ .reg .u64 t; cvta.to.shared.u64 t, %1; cvt.u32.u64 %0, t; }" : "=r"(a) : "l"(p));
    return a;
}
__device__ __forceinline__ void cp16(uint32_t dst, const void* src) {
    asm volatile("cp.async.cg.shared.global [%0], [%1], 16;" :: "r"(dst), "l"(src));
}
#define CP_COMMIT() asm volatile("cp.async.commit_group;" ::: "memory")
#define CP_WAIT1()  asm volatile("cp.async.wait_group 1;" ::: "memory")

__device__ __forceinline__ void mma_f16(float* d, const unsigned* a, const unsigned* b) {
    asm volatile(
        "mma.sync.aligned.m16n8k16.row.col.f32.f16.f16.f32 "
        "{%0,%1,%2,%3}, {%4,%5,%6,%7}, {%8,%9}, {%0,%1,%2,%3};\n"
        : "+f"(d[0]), "+f"(d[1]), "+f"(d[2]), "+f"(d[3])
        : "r"(a[0]), "r"(a[1]), "r"(a[2]), "r"(a[3]), "r"(b[0]), "r"(b[1]));
}

// ---------------- zero / init ----------------
__global__ void zero_out_kernel(float* out, int n) {
    int i = blockIdx.x * blockDim.x + threadIdx.x;
    int stride = gridDim.x * blockDim.x;
    if (i < NE) g_count[i] = 0;
    for (; i < n; i += stride) out[i] = 0.0f;
}

// ---------------- fp32 -> fp16 conversion (grid-stride over float4) ----------------
__global__ void cvt_f2h_kernel(const float4* __restrict__ src, uint2* __restrict__ dst,
                               size_t n4) {
    size_t i = (size_t)blockIdx.x * blockDim.x + threadIdx.x;
    size_t stride = (size_t)gridDim.x * blockDim.x;
    for (; i < n4; i += stride) dst[i] = cvt4h(src[i]);
}

// ---------------- gating: logits, softmax, top-2, routing ----------------
__global__ __launch_bounds__(256) void gating_kernel(const float* __restrict__ x,
                                                     const float* __restrict__ gw) {
    __shared__ float sgw[NE * H];
    for (int i = threadIdx.x; i < NE * H; i += blockDim.x) sgw[i] = gw[i];
    __syncthreads();

    int warp = threadIdx.x >> 5, lane = threadIdx.x & 31;
    int t = blockIdx.x * 8 + warp;
    const float* xr = x + (size_t)t * H;

    float acc[NE];
#pragma unroll
    for (int e = 0; e < NE; e++) acc[e] = 0.0f;
    for (int k = lane; k < H; k += 32) {
        float xv = xr[k];
#pragma unroll
        for (int e = 0; e < NE; e++) acc[e] += xv * sgw[e * H + k];
    }
#pragma unroll
    for (int e = 0; e < NE; e++)
#pragma unroll
        for (int off = 16; off; off >>= 1)
            acc[e] += __shfl_xor_sync(0xffffffffu, acc[e], off);

    if (lane == 0) {
        float mx = acc[0];
#pragma unroll
        for (int e = 1; e < NE; e++) mx = fmaxf(mx, acc[e]);
        float p[NE], s = 0.0f;
#pragma unroll
        for (int e = 0; e < NE; e++) { p[e] = expf(acc[e] - mx); s += p[e]; }
        float inv = 1.0f / s;
#pragma unroll
        for (int e = 0; e < NE; e++) { p[e] *= inv; g_probs[t * NE + e] = p[e]; }

        int b0 = 0;
#pragma unroll
        for (int e = 1; e < NE; e++) if (p[e] > p[b0]) b0 = e;
        int b1 = (b0 == 0) ? 1 : 0;
#pragma unroll
        for (int e = 0; e < NE; e++) if (e != b0 && p[e] > p[b1]) b1 = e;

        float d = 1.0f / (p[b0] + p[b1] + 1e-9f);
        int pos0 = atomicAdd(&g_count[b0], 1);
        g_tok[b0 * T_TOK + pos0] = t;
        g_wt[b0 * T_TOK + pos0] = p[b0] * d;
        int pos1 = atomicAdd(&g_count[b1], 1);
        g_tok[b1 * T_TOK + pos1] = t;
        g_wt[b1 * T_TOK + pos1] = p[b1] * d;
    }
}

// ---------------- prefix scan + aux loss ----------------
__global__ void scan_aux_kernel(float* out) {
    __shared__ float red[256];
    __shared__ float imp[NE];
    float s[NE];
#pragma unroll
    for (int e = 0; e < NE; e++) s[e] = 0.0f;
    for (int i = threadIdx.x; i < T_TOK; i += 256)
#pragma unroll
        for (int e = 0; e < NE; e++) s[e] += g_probs[i * NE + e];
    for (int e = 0; e < NE; e++) {
        red[threadIdx.x] = s[e];
        __syncthreads();
        for (int off = 128; off; off >>= 1) {
            if (threadIdx.x < off) red[threadIdx.x] += red[threadIdx.x + off];
            __syncthreads();
        }
        if (threadIdx.x == 0) imp[e] = red[0];
        __syncthreads();
    }
    if (threadIdx.x == 0) {
        int b = 0;
        float aux = 0.0f;
        for (int e = 0; e < NE; e++) {
            g_base[e] = b;
            b += g_count[e];
            float usage = (float)g_count[e] / ((float)(T_TOK * 2) + 1e-9f);
            aux += usage * (imp[e] / (float)T_TOK);
        }
        out[(size_t)T_TOK * H] = fminf(aux * (float)NE * 0.01f, 1.0f);
    }
}

// ---------------- GEMM tiling constants ----------------
#define BK 32
#define KS2 40     // half stride per smem row (80B, 16B aligned, conflict-benign)
#define KS2W 20    // b32 words per row
#define NSTG 3

// ---------------- GEMM1: h = silu(x@Wg^T) * (x@Wu^T) ----------------
#define BM1 128
#define BN1 64
#define G1_STGH ((BM1 + 2 * BN1) * KS2)           // halves per stage: 10240
#define G1_SMEM (512 + NSTG * G1_STGH * 2)        // 512B token table + 61440B

__global__ __launch_bounds__(256, 2) void gemm1_kernel(const __half* __restrict__ xh,
                                                       const __half* __restrict__ w1h) {
    int e = blockIdx.z;
    int cnt = g_count[e];
    int m0 = blockIdx.x * BM1;
    if (m0 >= cnt) return;
    int n0 = blockIdx.y * BN1;

    extern __shared__ __align__(16) char smraw[];
    int* stok = (int*)smraw;
    __half* stg = (__half*)(smraw + 512);
    uint32_t stg_b = smem_u32(stg);

    int tid = threadIdx.x, warp = tid >> 5, lane = tid & 31;
    int g4 = lane >> 2, tig = lane & 3;
    int wm = warp >> 1, wn = warp & 1;

    if (tid < BM1) {
        int p = m0 + tid;
        stok[tid] = (p < cnt) ? g_tok[e * T_TOK + p] : 0;
    }
    __syncthreads();

    // per-thread copy plan: 4 x 16B chunks per stage (1024 chunks total)
    const __half* srcb[4];
    uint32_t dsto[4];
#pragma unroll
    for (int t = 0; t < 4; t++) {
        int idx = tid + 256 * t;
        if (idx < 512) {                       // A: 128 rows x 4 chunks
            int r = idx >> 2, c = idx & 3;
            srcb[t] = xh + (size_t)stok[r] * H + c * 8;
            dsto[t] = (r * KS2 + c * 8) * 2;
        } else if (idx < 768) {                // Bg: 64 rows x 4 chunks
            int j = idx - 512;
            int r = j >> 2, c = j & 3;
            srcb[t] = w1h + (size_t)e * 2 * IDIM * H + (size_t)(n0 + r) * H + c * 8;
            dsto[t] = ((BM1 + r) * KS2 + c * 8) * 2;
        } else {                               // Bu: 64 rows x 4 chunks
            int j = idx - 768;
            int r = j >> 2, c = j & 3;
            srcb[t] = w1h + (size_t)e * 2 * IDIM * H + (size_t)(IDIM + n0 + r) * H + c * 8;
            dsto[t] = ((BM1 + BN1 + r) * KS2 + c * 8) * 2;
        }
    }

    const int NKT = H / BK;  // 32
    // prologue: stages 0,1
#pragma unroll
    for (int s = 0; s < 2; s++) {
        uint32_t db = stg_b + s * G1_STGH * 2;
#pragma unroll
        for (int t = 0; t < 4; t++) cp16(db + dsto[t], srcb[t] + s * BK);
        CP_COMMIT();
    }

    float accg[2][4][4], accu[2][4][4];
#pragma unroll
    for (int a = 0; a < 2; a++)
#pragma unroll
        for (int b = 0; b < 4; b++)
#pragma unroll
            for (int c = 0; c < 4; c++) { accg[a][b][c] = 0.0f; accu[a][b][c] = 0.0f; }

    for (int kt = 0; kt < NKT; kt++) {
        CP_WAIT1();
        __syncthreads();
        if (kt + 2 < NKT) {
            int s = (kt + 2) % NSTG;
            uint32_t db = stg_b + s * G1_STGH * 2;
#pragma unroll
            for (int t = 0; t < 4; t++) cp16(db + dsto[t], srcb[t] + (kt + 2) * BK);
            CP_COMMIT();
        }
        uint32_t* As32 = (uint32_t*)(stg + (kt % NSTG) * G1_STGH);
        uint32_t* Bg32 = As32 + BM1 * KS2W;
        uint32_t* Bu32 = Bg32 + BN1 * KS2W;
#pragma unroll
        for (int ks = 0; ks < 2; ks++) {
            int kw = ks * 8;
            unsigned a[2][4];
#pragma unroll
            for (int mf = 0; mf < 2; mf++) {
                int r = wm * 32 + mf * 16;
                int w0 = (r + g4) * KS2W + kw + tig;
                int w1r = (r + g4 + 8) * KS2W + kw + tig;
                a[mf][0] = As32[w0];
                a[mf][1] = As32[w1r];
                a[mf][2] = As32[w0 + 4];
                a[mf][3] = As32[w1r + 4];
            }
            unsigned bg[4][2], bu[4][2];
#pragma unroll
            for (int nf = 0; nf < 4; nf++) {
                int c = wn * 32 + nf * 8 + g4;
                int w0 = c * KS2W + kw + tig;
                bg[nf][0] = Bg32[w0];
                bg[nf][1] = Bg32[w0 + 4];
                bu[nf][0] = Bu32[w0];
                bu[nf][1] = Bu32[w0 + 4];
            }
#pragma unroll
            for (int mf = 0; mf < 2; mf++)
#pragma unroll
                for (int nf = 0; nf < 4; nf++) {
                    mma_f16(accg[mf][nf], a[mf], bg[nf]);
                    mma_f16(accu[mf][nf], a[mf], bu[nf]);
                }
        }
        __syncthreads();
    }

    // epilogue: silu(g)*u -> fp16, stage through smem (stride 72 halves)
    __half* Hs = stg;  // 128*72 = 9216 halves, fits in stage area
#pragma unroll
    for (int mf = 0; mf < 2; mf++)
#pragma unroll
        for (int nf = 0; nf < 4; nf++)
#pragma unroll
            for (int hh = 0; hh < 2; hh++) {
                int row = wm * 32 + mf * 16 + g4 + hh * 8;
                int col = wn * 32 + nf * 8 + tig * 2;
                float gv0 = accg[mf][nf][hh * 2 + 0], uv0 = accu[mf][nf][hh * 2 + 0];
                float gv1 = accg[mf][nf][hh * 2 + 1], uv1 = accu[mf][nf][hh * 2 + 1];
                float h0 = gv0 / (1.0f + __expf(-gv0)) * uv0;
                float h1 = gv1 / (1.0f + __expf(-gv1)) * uv1;
                *(uint32_t*)&Hs[row * 72 + col] = h2pack(h0, h1);
            }
    __syncthreads();

    int mybase = g_base[e];
#pragma unroll
    for (int t = 0; t < 4; t++) {
        int idx = tid + t * 256;
        int r = idx >> 3, c8 = idx & 7;
        if (m0 + r < cnt) {
            uint4 v = *(uint4*)&Hs[r * 72 + c8 * 8];
            *(uint4*)&g_h[(size_t)(mybase + m0 + r) * IDIM + n0 + c8 * 8] = v;
        }
    }
}

// ---------------- GEMM2: out[tok] += w * (h @ W2^T) ----------------
#define BM2 128
#define BN2 128
#define G2_STGH ((BM2 + BN2) * KS2)          // 10240 halves per stage
#define G2_SMEM (NSTG * G2_STGH * 2)         // 61440 B

__global__ __launch_bounds__(256, 2) void gemm2_kernel(const __half* __restrict__ w2h,
                                                       float* __restrict__ out) {
    int e = blockIdx.z;
    int cnt = g_count[e];
    int m0 = blockIdx.x * BM2;
    if (m0 >= cnt) return;
    int n0 = blockIdx.y * BN2;
    int base = g_base[e];

    extern __shared__ __align__(16) char smraw[];
    __half* stg = (__half*)smraw;
    uint32_t stg_b = smem_u32(stg);

    int tid = threadIdx.x, warp = tid >> 5, lane = tid & 31;
    int g4 = lane >> 2, tig = lane & 3;
    int wm = warp >> 1, wn = warp & 1;

    const __half* Ab = g_h + (size_t)(base + m0) * IDIM;

    const __half* srcb[4];
    uint32_t dsto[4];
#pragma unroll
    for (int t = 0; t < 4; t++) {
        int idx = tid + 256 * t;
        if (idx < 512) {                       // A: 128 rows x 4 chunks
            int r = idx >> 2, c = idx & 3;
            srcb[t] = Ab + (size_t)r * IDIM + c * 8;
            dsto[t] = (r * KS2 + c * 8) * 2;
        } else {                               // B: 128 rows x 4 chunks
            int j = idx - 512;
            int r = j >> 2, c = j & 3;
            srcb[t] = w2h + ((size_t)e * H + n0 + r) * IDIM + c * 8;
            dsto[t] = ((BM2 + r) * KS2 + c * 8) * 2;
        }
    }

    const int NKT = IDIM / BK;  // 128
#pragma unroll
    for (int s = 0; s < 2; s++) {
        uint32_t db = stg_b + s * G2_STGH * 2;
#pragma unroll
        for (int t = 0; t < 4; t++) cp16(db + dsto[t], srcb[t] + s * BK);
        CP_COMMIT();
    }

    float acc[2][8][4];
#pragma unroll
    for (int a = 0; a < 2; a++)
#pragma unroll
        for (int b = 0; b < 8; b++)
#pragma unroll
            for (int c = 0; c < 4; c++) acc[a][b][c] = 0.0f;

    for (int kt = 0; kt < NKT; kt++) {
        CP_WAIT1();
        __syncthreads();
        if (kt + 2 < NKT) {
            int s = (kt + 2) % NSTG;
            uint32_t db = stg_b + s * G2_STGH * 2;
#pragma unroll
            for (int t = 0; t < 4; t++) cp16(db + dsto[t], srcb[t] + (kt + 2) * BK);
            CP_COMMIT();
        }
        uint32_t* As32 = (uint32_t*)(stg + (kt % NSTG) * G2_STGH);
        uint32_t* Bs32 = As32 + BM2 * KS2W;
#pragma unroll
        for (int ks = 0; ks < 2; ks++) {
            int kw = ks * 8;
            unsigned a[2][4];
#pragma unroll
            for (int mf = 0; mf < 2; mf++) {
                int r = wm * 32 + mf * 16;
                int w0 = (r + g4) * KS2W + kw + tig;
                int w1r = (r + g4 + 8) * KS2W + kw + tig;
                a[mf][0] = As32[w0];
                a[mf][1] = As32[w1r];
                a[mf][2] = As32[w0 + 4];
                a[mf][3] = As32[w1r + 4];
            }
            unsigned b[8][2];
#pragma unroll
            for (int nf = 0; nf < 8; nf++) {
                int c = wn * 64 + nf * 8 + g4;
                int w0 = c * KS2W + kw + tig;
                b[nf][0] = Bs32[w0];
                b[nf][1] = Bs32[w0 + 4];
            }
#pragma unroll
            for (int mf = 0; mf < 2; mf++)
#pragma unroll
                for (int nf = 0; nf < 8; nf++) mma_f16(acc[mf][nf], a[mf], b[nf]);
        }
        __syncthreads();
    }

    // epilogue: weighted scatter-add (exactly 2 adds per out element)
#pragma unroll
    for (int mf = 0; mf < 2; mf++) {
#pragma unroll
        for (int half = 0; half < 2; half++) {
            int r = wm * 32 + mf * 16 + g4 + half * 8;
            int gr = m0 + r;
            if (gr < cnt) {
                int tok = g_tok[e * T_TOK + gr];
                float w = g_wt[e * T_TOK + gr];
                float* op = out + (size_t)tok * H + n0 + wn * 64;
#pragma unroll
                for (int nf = 0; nf < 8; nf++) {
                    atomicAdd(op + nf * 8 + tig * 2, w * acc[mf][nf][half * 2 + 0]);
                    atomicAdd(op + nf * 8 + tig * 2 + 1, w * acc[mf][nf][half * 2 + 1]);
                }
            }
        }
    }
}

// ---------------- launch ----------------
extern "C" void kernel_launch(void* const* d_in, const int* in_sizes, int n_in,
                              void* d_out, int out_size) {
    const float* x = (const float*)d_in[0];
    const float* gate_w = (const float*)d_in[1];
    const float* gate_up_w = (const float*)d_in[2];
    const float* down_w = (const float*)d_in[3];
    float* out = (float*)d_out;

    static int attr_done = 0;
    if (!attr_done) {
        cudaFuncSetAttribute(gemm1_kernel, cudaFuncAttributeMaxDynamicSharedMemorySize, G1_SMEM);
        cudaFuncSetAttribute(gemm2_kernel, cudaFuncAttributeMaxDynamicSharedMemorySize, G2_SMEM);
        attr_done = 1;
    }

    zero_out_kernel<<<4096, 256>>>(out, out_size);

    // fp32 -> fp16 conversions
    __half* xh_p;   cudaGetSymbolAddress((void**)&xh_p, g_xh);
    __half* w1h_p;  cudaGetSymbolAddress((void**)&w1h_p, g_w1h);
    __half* w2h_p;  cudaGetSymbolAddress((void**)&w2h_p, g_w2h);
    cvt_f2h_kernel<<<2048, 256>>>((const float4*)x, (uint2*)xh_p, (size_t)T_TOK * H / 4);
    cvt_f2h_kernel<<<8192, 256>>>((const float4*)gate_up_w, (uint2*)w1h_p,
                                  (size_t)NE * 2 * IDIM * H / 4);
    cvt_f2h_kernel<<<4096, 256>>>((const float4*)down_w, (uint2*)w2h_p,
                                  (size_t)NE * H * IDIM / 4);

    gating_kernel<<<T_TOK / 8, 256>>>(x, gate_w);
    scan_aux_kernel<<<1, 256>>>(out);

    dim3 g1(T_TOK / BM1, IDIM / BN1, NE);  // (64, 64, 8)
    gemm1_kernel<<<g1, 256, G1_SMEM>>>(xh_p, w1h_p);

    dim3 g2(T_TOK / BM2, H / BN2, NE);     // (64, 8, 8)
    gemm2_kernel<<<g2, 256, G2_SMEM>>>(w2h_p, out);
}

// round 13
// speedup vs baseline: 3.6567x; 1.2022x over previous
#include <cuda_runtime.h>
#include <cuda_fp16.h>
#include <cstdint>
#include <math.h>

#define H 1024
#define IDIM 4096
#define NE 8
#define T_TOK 8192
#define NSLOT (2 * T_TOK)

// ---------------- device scratch ----------------
__device__ int    g_count[NE];
__device__ int    g_base[NE];
__device__ int    g_tok[NE * T_TOK];
__device__ float  g_wt[NE * T_TOK];
__device__ float  g_probs[T_TOK * NE];
__device__ __half g_h[(size_t)(NSLOT + 128) * IDIM];     // hidden acts (fp16)
__device__ __half g_xh[(size_t)T_TOK * H];               // x in fp16
__device__ __half g_w1h[(size_t)NE * 2 * IDIM * H];      // gate_up_w fp16
__device__ __half g_w2h[(size_t)NE * H * IDIM];          // down_w fp16

// ---------------- helpers ----------------
__device__ __forceinline__ uint32_t h2pack(float a, float b) {
    __half2 h = __floats2half2_rn(a, b);
    return *(uint32_t*)&h;
}
__device__ __forceinline__ uint2 cvt4h(float4 v) {
    return make_uint2(h2pack(v.x, v.y), h2pack(v.z, v.w));
}
__device__ __forceinline__ uint32_t smem_u32(const void* p) {
    uint32_t a;
    asm("{ .reg .u64 t; cvta.to.shared.u64 t, %1; cvt.u32.u64 %0, t; }" : "=r"(a) : "l"(p));
    return a;
}
__device__ __forceinline__ void cp16(uint32_t dst, const void* src) {
    asm volatile("cp.async.cg.shared.global [%0], [%1], 16;" :: "r"(dst), "l"(src));
}
#define CP_COMMIT() asm volatile("cp.async.commit_group;" ::: "memory")
#define CP_WAIT2()  asm volatile("cp.async.wait_group 2;" ::: "memory")

__device__ __forceinline__ void mma_f16(float* d, const unsigned* a, const unsigned* b) {
    asm volatile(
        "mma.sync.aligned.m16n8k16.row.col.f32.f16.f16.f32 "
        "{%0,%1,%2,%3}, {%4,%5,%6,%7}, {%8,%9}, {%0,%1,%2,%3};\n"
        : "+f"(d[0]), "+f"(d[1]), "+f"(d[2]), "+f"(d[3])
        : "r"(a[0]), "r"(a[1]), "r"(a[2]), "r"(a[3]), "r"(b[0]), "r"(b[1]));
}
__device__ __forceinline__ void ldsm_x4(unsigned* r, uint32_t addr) {
    asm volatile("ldmatrix.sync.aligned.m8n8.x4.shared.b16 {%0,%1,%2,%3}, [%4];"
                 : "=r"(r[0]), "=r"(r[1]), "=r"(r[2]), "=r"(r[3]) : "r"(addr));
}

// ---------------- zero / init ----------------
__global__ void zero_out_kernel(float* out, int n) {
    int i = blockIdx.x * blockDim.x + threadIdx.x;
    int stride = gridDim.x * blockDim.x;
    if (i < NE) g_count[i] = 0;
    for (; i < n; i += stride) out[i] = 0.0f;
}

// ---------------- fp32 -> fp16 conversion ----------------
__global__ void cvt_f2h_kernel(const float4* __restrict__ src, uint2* __restrict__ dst,
                               size_t n4) {
    size_t i = (size_t)blockIdx.x * blockDim.x + threadIdx.x;
    size_t stride = (size_t)gridDim.x * blockDim.x;
    for (; i < n4; i += stride) dst[i] = cvt4h(src[i]);
}

// ---------------- gating: logits, softmax, top-2, routing ----------------
__global__ __launch_bounds__(256) void gating_kernel(const float* __restrict__ x,
                                                     const float* __restrict__ gw) {
    __shared__ float sgw[NE * H];
    for (int i = threadIdx.x; i < NE * H; i += blockDim.x) sgw[i] = gw[i];
    __syncthreads();

    int warp = threadIdx.x >> 5, lane = threadIdx.x & 31;
    int t = blockIdx.x * 8 + warp;
    const float* xr = x + (size_t)t * H;

    float acc[NE];
#pragma unroll
    for (int e = 0; e < NE; e++) acc[e] = 0.0f;
    for (int k = lane; k < H; k += 32) {
        float xv = xr[k];
#pragma unroll
        for (int e = 0; e < NE; e++) acc[e] += xv * sgw[e * H + k];
    }
#pragma unroll
    for (int e = 0; e < NE; e++)
#pragma unroll
        for (int off = 16; off; off >>= 1)
            acc[e] += __shfl_xor_sync(0xffffffffu, acc[e], off);

    if (lane == 0) {
        float mx = acc[0];
#pragma unroll
        for (int e = 1; e < NE; e++) mx = fmaxf(mx, acc[e]);
        float p[NE], s = 0.0f;
#pragma unroll
        for (int e = 0; e < NE; e++) { p[e] = expf(acc[e] - mx); s += p[e]; }
        float inv = 1.0f / s;
#pragma unroll
        for (int e = 0; e < NE; e++) { p[e] *= inv; g_probs[t * NE + e] = p[e]; }

        int b0 = 0;
#pragma unroll
        for (int e = 1; e < NE; e++) if (p[e] > p[b0]) b0 = e;
        int b1 = (b0 == 0) ? 1 : 0;
#pragma unroll
        for (int e = 0; e < NE; e++) if (e != b0 && p[e] > p[b1]) b1 = e;

        float d = 1.0f / (p[b0] + p[b1] + 1e-9f);
        int pos0 = atomicAdd(&g_count[b0], 1);
        g_tok[b0 * T_TOK + pos0] = t;
        g_wt[b0 * T_TOK + pos0] = p[b0] * d;
        int pos1 = atomicAdd(&g_count[b1], 1);
        g_tok[b1 * T_TOK + pos1] = t;
        g_wt[b1 * T_TOK + pos1] = p[b1] * d;
    }
}

// ---------------- prefix scan + aux loss ----------------
__global__ void scan_aux_kernel(float* out) {
    __shared__ float red[256];
    __shared__ float imp[NE];
    float s[NE];
#pragma unroll
    for (int e = 0; e < NE; e++) s[e] = 0.0f;
    for (int i = threadIdx.x; i < T_TOK; i += 256)
#pragma unroll
        for (int e = 0; e < NE; e++) s[e] += g_probs[i * NE + e];
    for (int e = 0; e < NE; e++) {
        red[threadIdx.x] = s[e];
        __syncthreads();
        for (int off = 128; off; off >>= 1) {
            if (threadIdx.x < off) red[threadIdx.x] += red[threadIdx.x + off];
            __syncthreads();
        }
        if (threadIdx.x == 0) imp[e] = red[0];
        __syncthreads();
    }
    if (threadIdx.x == 0) {
        int b = 0;
        float aux = 0.0f;
        for (int e = 0; e < NE; e++) {
            g_base[e] = b;
            b += g_count[e];
            float usage = (float)g_count[e] / ((float)(T_TOK * 2) + 1e-9f);
            aux += usage * (imp[e] / (float)T_TOK);
        }
        out[(size_t)T_TOK * H] = fminf(aux * (float)NE * 0.01f, 1.0f);
    }
}

// ---------------- GEMM tiling constants ----------------
#define BK 32
#define KS2 40     // half stride per smem row (80B): LDSM phases hit all 32 banks
#define NSTG 4

// ---------------- GEMM1: h = silu(x@Wg^T) * (x@Wu^T) ----------------
#define BM1 128
#define BN1 64
#define G1_STGH ((BM1 + 2 * BN1) * KS2)           // 10240 halves / stage
#define G1_SMEM (512 + NSTG * G1_STGH * 2)        // 82432 B

__global__ __launch_bounds__(256, 2) void gemm1_kernel(const __half* __restrict__ xh,
                                                       const __half* __restrict__ w1h) {
    int e = blockIdx.z;
    int cnt = g_count[e];
    int m0 = blockIdx.x * BM1;
    if (m0 >= cnt) return;
    int n0 = blockIdx.y * BN1;

    extern __shared__ __align__(16) char smraw[];
    int* stok = (int*)smraw;
    __half* stg = (__half*)(smraw + 512);
    uint32_t stg_b = smem_u32(stg);

    int tid = threadIdx.x, warp = tid >> 5, lane = tid & 31;
    int wm = warp >> 1, wn = warp & 1;

    if (tid < BM1) {
        int p = m0 + tid;
        stok[tid] = (p < cnt) ? g_tok[e * T_TOK + p] : 0;
    }
    __syncthreads();

    // per-thread cp.async plan: 4 x 16B chunks / stage
    const __half* srcb[4];
    uint32_t dsto[4];
#pragma unroll
    for (int t = 0; t < 4; t++) {
        int idx = tid + 256 * t;
        if (idx < 512) {
            int r = idx >> 2, c = idx & 3;
            srcb[t] = xh + (size_t)stok[r] * H + c * 8;
            dsto[t] = (r * KS2 + c * 8) * 2;
        } else if (idx < 768) {
            int j = idx - 512;
            int r = j >> 2, c = j & 3;
            srcb[t] = w1h + (size_t)e * 2 * IDIM * H + (size_t)(n0 + r) * H + c * 8;
            dsto[t] = ((BM1 + r) * KS2 + c * 8) * 2;
        } else {
            int j = idx - 768;
            int r = j >> 2, c = j & 3;
            srcb[t] = w1h + (size_t)e * 2 * IDIM * H + (size_t)(IDIM + n0 + r) * H + c * 8;
            dsto[t] = ((BM1 + BN1 + r) * KS2 + c * 8) * 2;
        }
    }

    // ldmatrix half-offsets (within stage)
    uint32_t offA[2], offBg[2], offBu[2];
#pragma unroll
    for (int mf = 0; mf < 2; mf++)
        offA[mf] = (uint32_t)((wm * 32 + mf * 16 + (lane & 7) + ((lane >> 3) & 1) * 8) * KS2
                              + ((lane >> 4) & 1) * 8);
#pragma unroll
    for (int p = 0; p < 2; p++) {
        offBg[p] = (uint32_t)((BM1 + wn * 32 + p * 16 + (lane & 7) + ((lane >> 4) & 1) * 8) * KS2
                              + ((lane >> 3) & 1) * 8);
        offBu[p] = offBg[p] + BN1 * KS2;
    }

    const int NKT = H / BK;  // 32
#pragma unroll
    for (int s = 0; s < 3; s++) {
        uint32_t db = stg_b + s * G1_STGH * 2;
#pragma unroll
        for (int t = 0; t < 4; t++) cp16(db + dsto[t], srcb[t] + s * BK);
        CP_COMMIT();
    }

    float accg[2][4][4], accu[2][4][4];
#pragma unroll
    for (int a = 0; a < 2; a++)
#pragma unroll
        for (int b = 0; b < 4; b++)
#pragma unroll
            for (int c = 0; c < 4; c++) { accg[a][b][c] = 0.0f; accu[a][b][c] = 0.0f; }

    for (int kt = 0; kt < NKT; kt++) {
        CP_WAIT2();
        __syncthreads();
        if (kt + 3 < NKT) {
            int s = (kt + 3) % NSTG;
            uint32_t db = stg_b + s * G1_STGH * 2;
#pragma unroll
            for (int t = 0; t < 4; t++) cp16(db + dsto[t], srcb[t] + (kt + 3) * BK);
            CP_COMMIT();
        }
        uint32_t base_b = stg_b + (kt % NSTG) * G1_STGH * 2;
#pragma unroll
        for (int ks = 0; ks < 2; ks++) {
            uint32_t kb = base_b + ks * 32;  // ks*16 halves
            unsigned a[2][4], bg[4][2], bu[4][2];
            ldsm_x4(a[0], kb + offA[0] * 2);
            ldsm_x4(a[1], kb + offA[1] * 2);
            ldsm_x4(&bg[0][0], kb + offBg[0] * 2);
            ldsm_x4(&bg[2][0], kb + offBg[1] * 2);
            ldsm_x4(&bu[0][0], kb + offBu[0] * 2);
            ldsm_x4(&bu[2][0], kb + offBu[1] * 2);
#pragma unroll
            for (int mf = 0; mf < 2; mf++)
#pragma unroll
                for (int nf = 0; nf < 4; nf++) {
                    mma_f16(accg[mf][nf], a[mf], bg[nf]);
                    mma_f16(accu[mf][nf], a[mf], bu[nf]);
                }
        }
        __syncthreads();
    }

    // epilogue: silu(g)*u -> fp16, stage through smem (stride 72 halves)
    int g4 = lane >> 2, tig = lane & 3;
    __half* Hs = stg;
#pragma unroll
    for (int mf = 0; mf < 2; mf++)
#pragma unroll
        for (int nf = 0; nf < 4; nf++)
#pragma unroll
            for (int hh = 0; hh < 2; hh++) {
                int row = wm * 32 + mf * 16 + g4 + hh * 8;
                int col = wn * 32 + nf * 8 + tig * 2;
                float gv0 = accg[mf][nf][hh * 2 + 0], uv0 = accu[mf][nf][hh * 2 + 0];
                float gv1 = accg[mf][nf][hh * 2 + 1], uv1 = accu[mf][nf][hh * 2 + 1];
                float h0 = gv0 / (1.0f + __expf(-gv0)) * uv0;
                float h1 = gv1 / (1.0f + __expf(-gv1)) * uv1;
                *(uint32_t*)&Hs[row * 72 + col] = h2pack(h0, h1);
            }
    __syncthreads();

    int mybase = g_base[e];
#pragma unroll
    for (int t = 0; t < 4; t++) {
        int idx = tid + t * 256;
        int r = idx >> 3, c8 = idx & 7;
        if (m0 + r < cnt) {
            uint4 v = *(uint4*)&Hs[r * 72 + c8 * 8];
            *(uint4*)&g_h[(size_t)(mybase + m0 + r) * IDIM + n0 + c8 * 8] = v;
        }
    }
}

// ---------------- GEMM2: out[tok] += w * (h @ W2^T) ----------------
#define BM2 128
#define BN2 128
#define G2_STGH ((BM2 + BN2) * KS2)          // 10240 halves / stage
#define G2_SMEM (NSTG * G2_STGH * 2)         // 81920 B

__global__ __launch_bounds__(256, 2) void gemm2_kernel(const __half* __restrict__ w2h,
                                                       float* __restrict__ out) {
    int e = blockIdx.z;
    int cnt = g_count[e];
    int m0 = blockIdx.x * BM2;
    if (m0 >= cnt) return;
    int n0 = blockIdx.y * BN2;
    int base = g_base[e];

    extern __shared__ __align__(16) char smraw[];
    __half* stg = (__half*)smraw;
    uint32_t stg_b = smem_u32(stg);

    int tid = threadIdx.x, warp = tid >> 5, lane = tid & 31;
    int wm = warp >> 1, wn = warp & 1;

    const __half* Ab = g_h + (size_t)(base + m0) * IDIM;

    const __half* srcb[4];
    uint32_t dsto[4];
#pragma unroll
    for (int t = 0; t < 4; t++) {
        int idx = tid + 256 * t;
        if (idx < 512) {
            int r = idx >> 2, c = idx & 3;
            srcb[t] = Ab + (size_t)r * IDIM + c * 8;
            dsto[t] = (r * KS2 + c * 8) * 2;
        } else {
            int j = idx - 512;
            int r = j >> 2, c = j & 3;
            srcb[t] = w2h + ((size_t)e * H + n0 + r) * IDIM + c * 8;
            dsto[t] = ((BM2 + r) * KS2 + c * 8) * 2;
        }
    }

    uint32_t offA[2], offB[4];
#pragma unroll
    for (int mf = 0; mf < 2; mf++)
        offA[mf] = (uint32_t)((wm * 32 + mf * 16 + (lane & 7) + ((lane >> 3) & 1) * 8) * KS2
                              + ((lane >> 4) & 1) * 8);
#pragma unroll
    for (int p = 0; p < 4; p++)
        offB[p] = (uint32_t)((BM2 + wn * 64 + p * 16 + (lane & 7) + ((lane >> 4) & 1) * 8) * KS2
                             + ((lane >> 3) & 1) * 8);

    const int NKT = IDIM / BK;  // 128
#pragma unroll
    for (int s = 0; s < 3; s++) {
        uint32_t db = stg_b + s * G2_STGH * 2;
#pragma unroll
        for (int t = 0; t < 4; t++) cp16(db + dsto[t], srcb[t] + s * BK);
        CP_COMMIT();
    }

    float acc[2][8][4];
#pragma unroll
    for (int a = 0; a < 2; a++)
#pragma unroll
        for (int b = 0; b < 8; b++)
#pragma unroll
            for (int c = 0; c < 4; c++) acc[a][b][c] = 0.0f;

    for (int kt = 0; kt < NKT; kt++) {
        CP_WAIT2();
        __syncthreads();
        if (kt + 3 < NKT) {
            int s = (kt + 3) % NSTG;
            uint32_t db = stg_b + s * G2_STGH * 2;
#pragma unroll
            for (int t = 0; t < 4; t++) cp16(db + dsto[t], srcb[t] + (kt + 3) * BK);
            CP_COMMIT();
        }
        uint32_t base_b = stg_b + (kt % NSTG) * G2_STGH * 2;
#pragma unroll
        for (int ks = 0; ks < 2; ks++) {
            uint32_t kb = base_b + ks * 32;
            unsigned a[2][4], b[8][2];
            ldsm_x4(a[0], kb + offA[0] * 2);
            ldsm_x4(a[1], kb + offA[1] * 2);
            ldsm_x4(&b[0][0], kb + offB[0] * 2);
            ldsm_x4(&b[2][0], kb + offB[1] * 2);
            ldsm_x4(&b[4][0], kb + offB[2] * 2);
            ldsm_x4(&b[6][0], kb + offB[3] * 2);
#pragma unroll
            for (int mf = 0; mf < 2; mf++)
#pragma unroll
                for (int nf = 0; nf < 8; nf++) mma_f16(acc[mf][nf], a[mf], b[nf]);
        }
        __syncthreads();
    }

    // epilogue: weighted scatter-add (exactly 2 adds per out element)
    int g4 = lane >> 2, tig = lane & 3;
#pragma unroll
    for (int mf = 0; mf < 2; mf++) {
#pragma unroll
        for (int half = 0; half < 2; half++) {
            int r = wm * 32 + mf * 16 + g4 + half * 8;
            int gr = m0 + r;
            if (gr < cnt) {
                int tok = g_tok[e * T_TOK + gr];
                float w = g_wt[e * T_TOK + gr];
                float* op = out + (size_t)tok * H + n0 + wn * 64;
#pragma unroll
                for (int nf = 0; nf < 8; nf++) {
                    atomicAdd(op + nf * 8 + tig * 2, w * acc[mf][nf][half * 2 + 0]);
                    atomicAdd(op + nf * 8 + tig * 2 + 1, w * acc[mf][nf][half * 2 + 1]);
                }
            }
        }
    }
}

// ---------------- launch ----------------
extern "C" void kernel_launch(void* const* d_in, const int* in_sizes, int n_in,
                              void* d_out, int out_size) {
    const float* x = (const float*)d_in[0];
    const float* gate_w = (const float*)d_in[1];
    const float* gate_up_w = (const float*)d_in[2];
    const float* down_w = (const float*)d_in[3];
    float* out = (float*)d_out;

    static int attr_done = 0;
    if (!attr_done) {
        cudaFuncSetAttribute(gemm1_kernel, cudaFuncAttributeMaxDynamicSharedMemorySize, G1_SMEM);
        cudaFuncSetAttribute(gemm2_kernel, cudaFuncAttributeMaxDynamicSharedMemorySize, G2_SMEM);
        attr_done = 1;
    }

    zero_out_kernel<<<4096, 256>>>(out, out_size);

    __half* xh_p;   cudaGetSymbolAddress((void**)&xh_p, g_xh);
    __half* w1h_p;  cudaGetSymbolAddress((void**)&w1h_p, g_w1h);
    __half* w2h_p;  cudaGetSymbolAddress((void**)&w2h_p, g_w2h);
    cvt_f2h_kernel<<<2048, 256>>>((const float4*)x, (uint2*)xh_p, (size_t)T_TOK * H / 4);
    cvt_f2h_kernel<<<8192, 256>>>((const float4*)gate_up_w, (uint2*)w1h_p,
                                  (size_t)NE * 2 * IDIM * H / 4);
    cvt_f2h_kernel<<<4096, 256>>>((const float4*)down_w, (uint2*)w2h_p,
                                  (size_t)NE * H * IDIM / 4);

    gating_kernel<<<T_TOK / 8, 256>>>(x, gate_w);
    scan_aux_kernel<<<1, 256>>>(out);

    dim3 g1(T_TOK / BM1, IDIM / BN1, NE);  // (64, 64, 8)
    gemm1_kernel<<<g1, 256, G1_SMEM>>>(xh_p, w1h_p);

    dim3 g2(T_TOK / BM2, H / BN2, NE);     // (64, 8, 8)
    gemm2_kernel<<<g2, 256, G2_SMEM>>>(w2h_p, out);
}